// round 1
// baseline (speedup 1.0000x reference)
#include <cuda_runtime.h>
#include <cuda_bf16.h>
#include <cstdint>

// AWQ int4 GEMM, fp32 SIMT baseline.
// out[M,N] = x[M,K] @ ((unpack(qweight) - unpack(qzeros)_bcast) * scales_bcast)
// Shapes fixed by the problem: M=2048, K=4096, N=11008, G=128.

namespace {
constexpr int M = 2048;
constexpr int K = 4096;
constexpr int N = 11008;
constexpr int G = 128;
constexpr int NP = N / 8;     // packed columns

constexpr int BM = 128;
constexpr int BN = 128;
constexpr int BK = 16;
constexpr int TM = 8;
constexpr int TN = 8;
constexpr int THREADS = (BM / TM) * (BN / TN);  // 256
}

__global__ __launch_bounds__(THREADS, 2)
void awq_gemm_f32_kernel(const float* __restrict__ x,
                         const int*   __restrict__ qw,
                         const int*   __restrict__ qz,
                         const float* __restrict__ sc,
                         float*       __restrict__ out)
{
    __shared__ float As[BK][BM + 4];   // +4 floats keeps 16B alignment for float4 reads
    __shared__ float Bs[BK][BN];
    __shared__ float zg[BN];
    __shared__ float sg[BN];

    const int bn  = blockIdx.x * BN;
    const int bm  = blockIdx.y * BM;
    const int tid = threadIdx.x;
    const int tm  = tid >> 4;          // 0..15: M-direction thread coord
    const int tn  = tid & 15;          // 0..15: N-direction thread coord

    const int brow = tid >> 4;         // dequant: k-row within tile (0..15)
    const int bpc  = tid & 15;         // dequant: packed-int32 column (0..15)

    float acc[TM][TN];
    #pragma unroll
    for (int i = 0; i < TM; ++i)
        #pragma unroll
        for (int j = 0; j < TN; ++j)
            acc[i][j] = 0.f;

    for (int g = 0; g < K / G; ++g) {
        // ---- Load group zeros & scales for columns [bn, bn+BN) ----
        if (tid < BN) {
            const int m = tid & 7;
            const int sh = ((m >> 1) << 2) + ((m & 1) << 4);   // AWQ inverse order * 4
            unsigned zw = (unsigned)qz[(size_t)g * NP + ((bn + tid) >> 3)];
            zg[tid] = (float)((zw >> sh) & 0xF);
            sg[tid] = sc[(size_t)g * N + bn + tid];
        }
        __syncthreads();

        #pragma unroll 1
        for (int kt = 0; kt < G / BK; ++kt) {
            const int k0 = g * G + kt * BK;

            // ---- Load A tile (128x16 fp32), store transposed As[k][m] ----
            #pragma unroll
            for (int i = 0; i < 2; ++i) {
                const int f   = tid + i * THREADS;   // 0..511 float4 slots
                const int row = f >> 2;
                const int c4  = (f & 3) << 2;
                float4 v = *reinterpret_cast<const float4*>(
                    &x[(size_t)(bm + row) * K + k0 + c4]);
                As[c4 + 0][row] = v.x;
                As[c4 + 1][row] = v.y;
                As[c4 + 2][row] = v.z;
                As[c4 + 3][row] = v.w;
            }

            // ---- Dequant B tile (16x128): one packed int32 per thread ----
            {
                unsigned w = (unsigned)qw[(size_t)(k0 + brow) * NP + (bn >> 3) + bpc];
                const int nb = bpc << 3;
                #pragma unroll
                for (int m = 0; m < 8; ++m) {
                    const int sh = ((m >> 1) << 2) + ((m & 1) << 4);
                    const int nl = nb + m;
                    Bs[brow][nl] = ((float)((w >> sh) & 0xF) - zg[nl]) * sg[nl];
                }
            }
            __syncthreads();

            // ---- 8x8 register-tile FMA over BK ----
            #pragma unroll
            for (int k = 0; k < BK; ++k) {
                float4 a0 = *reinterpret_cast<const float4*>(&As[k][tm * TM]);
                float4 a1 = *reinterpret_cast<const float4*>(&As[k][tm * TM + 4]);
                float4 b0 = *reinterpret_cast<const float4*>(&Bs[k][tn * TN]);
                float4 b1 = *reinterpret_cast<const float4*>(&Bs[k][tn * TN + 4]);
                float a[TM] = {a0.x, a0.y, a0.z, a0.w, a1.x, a1.y, a1.z, a1.w};
                float b[TN] = {b0.x, b0.y, b0.z, b0.w, b1.x, b1.y, b1.z, b1.w};
                #pragma unroll
                for (int i = 0; i < TM; ++i)
                    #pragma unroll
                    for (int j = 0; j < TN; ++j)
                        acc[i][j] = fmaf(a[i], b[j], acc[i][j]);
            }
            __syncthreads();
        }
    }

    // ---- Epilogue: vectorized fp32 stores ----
    #pragma unroll
    for (int i = 0; i < TM; ++i) {
        const size_t row = (size_t)(bm + tm * TM + i);
        #pragma unroll
        for (int j = 0; j < TN; j += 4) {
            float4 v = make_float4(acc[i][j], acc[i][j + 1],
                                   acc[i][j + 2], acc[i][j + 3]);
            *reinterpret_cast<float4*>(&out[row * N + bn + tn * TN + j]) = v;
        }
    }
}

extern "C" void kernel_launch(void* const* d_in, const int* in_sizes, int n_in,
                              void* d_out, int out_size)
{
    const float* x  = (const float*)d_in[0];
    const int*   qw = (const int*)  d_in[1];
    const int*   qz = (const int*)  d_in[2];
    const float* sc = (const float*)d_in[3];
    float*       out = (float*)d_out;

    dim3 grid(N / BN, M / BM);   // 86 x 16
    awq_gemm_f32_kernel<<<grid, THREADS>>>(x, qw, qz, sc, out);
}

// round 4
// speedup vs baseline: 7.2472x; 7.2472x over previous
#include <cuda_runtime.h>
#include <cuda_fp16.h>
#include <cstdint>

// AWQ int4 GEMM via ldmatrix + mma.sync.m16n8k16 (fp16 in, fp32 accum).
// out = x @ ((q - z) * s).  M=2048, K=4096, N=11008, G=128.
// x pre-converted to fp16 once; w dequantized in-kernel to fp16.

namespace {
constexpr int MM = 2048, KK = 4096, NN = 11008, G = 128;
constexpr int NP = NN / 8;
constexpr int BM = 128, BN = 128, BK = 32;
constexpr int THREADS = 256;
constexpr int KTILES = KK / BK;          // 128
constexpr int AK = BK + 8;               // padded A row stride (halves)
constexpr int BNP = BN + 8;              // padded B row stride (halves)
}

__device__ __half g_xh[(size_t)MM * KK];   // fp16 copy of x

__device__ __forceinline__ uint32_t smem_u32(const void* p) {
    uint32_t a;
    asm("{ .reg .u64 t; cvta.to.shared.u64 t, %1; cvt.u32.u64 %0, t; }" : "=r"(a) : "l"(p));
    return a;
}
__device__ __forceinline__ void cp_async16(uint32_t dst, const void* src) {
    asm volatile("cp.async.ca.shared.global [%0], [%1], 16;" :: "r"(dst), "l"(src));
}
__device__ __forceinline__ void cp_commit() {
    asm volatile("cp.async.commit_group;" ::: "memory");
}
template <int N_> __device__ __forceinline__ void cp_wait() {
    asm volatile("cp.async.wait_group %0;" :: "n"(N_) : "memory");
}
__device__ __forceinline__ void ldsm_x4(uint32_t* r, uint32_t addr) {
    asm volatile("ldmatrix.sync.aligned.m8n8.x4.shared.b16 {%0,%1,%2,%3}, [%4];"
                 : "=r"(r[0]), "=r"(r[1]), "=r"(r[2]), "=r"(r[3]) : "r"(addr));
}
__device__ __forceinline__ void ldsm_x4_t(uint32_t* r, uint32_t addr) {
    asm volatile("ldmatrix.sync.aligned.m8n8.x4.trans.shared.b16 {%0,%1,%2,%3}, [%4];"
                 : "=r"(r[0]), "=r"(r[1]), "=r"(r[2]), "=r"(r[3]) : "r"(addr));
}
__device__ __forceinline__ void mma16816(float* c, const uint32_t* a, const uint32_t* b) {
    asm volatile(
        "mma.sync.aligned.m16n8k16.row.col.f32.f16.f16.f32 "
        "{%0,%1,%2,%3}, {%4,%5,%6,%7}, {%8,%9}, {%0,%1,%2,%3};"
        : "+f"(c[0]), "+f"(c[1]), "+f"(c[2]), "+f"(c[3])
        : "r"(a[0]), "r"(a[1]), "r"(a[2]), "r"(a[3]), "r"(b[0]), "r"(b[1]));
}
__device__ __forceinline__ int awq_shift(int j) {
    return ((j >> 1) << 2) | ((j & 1) << 4);
}

// ---------------- preprocess: x fp32 -> fp16 ----------------
__global__ __launch_bounds__(256) void conv_x_kernel(const float* __restrict__ x) {
    size_t idx = (size_t)blockIdx.x * 256 + threadIdx.x;   // 8 elements each
    const float4* xp = reinterpret_cast<const float4*>(x);
    float4 f0 = xp[idx * 2 + 0];
    float4 f1 = xp[idx * 2 + 1];
    __half2 h0 = __floats2half2_rn(f0.x, f0.y);
    __half2 h1 = __floats2half2_rn(f0.z, f0.w);
    __half2 h2 = __floats2half2_rn(f1.x, f1.y);
    __half2 h3 = __floats2half2_rn(f1.z, f1.w);
    uint4 v = make_uint4(*reinterpret_cast<uint32_t*>(&h0), *reinterpret_cast<uint32_t*>(&h1),
                         *reinterpret_cast<uint32_t*>(&h2), *reinterpret_cast<uint32_t*>(&h3));
    reinterpret_cast<uint4*>(g_xh)[idx] = v;
}

// ---------------- main GEMM ----------------
__global__ __launch_bounds__(THREADS)
void awq_mma_kernel(const int* __restrict__ qw, const int* __restrict__ qz,
                    const float* __restrict__ sc, float* __restrict__ out)
{
    __shared__ __half As[2][BM][AK];
    __shared__ __half Bs[2][BK][BNP];

    const int tid  = threadIdx.x;
    const int lane = tid & 31;
    const int warp = tid >> 5;
    const int wm   = warp & 3;           // m warp coord (4)
    const int wn   = warp >> 2;          // n warp coord (2)
    const int bn   = blockIdx.x * BN;
    const int bm   = blockIdx.y * BM;

    // A-load mapping: 512 16B chunks/stage, 2 per thread
    const int ar = tid >> 2;             // row 0..63 (+64 for i=1)
    const int ac = (tid & 3) * 8;        // k col in halves

    // dequant mapping: word (k, pc), pc fixed per thread
    const int pc = tid & 15;             // packed col 0..15
    const int kq = tid >> 4;             // k 0..15 (+16 for i=1)

    const uint32_t as_base[2] = { smem_u32(&As[0][0][0]), smem_u32(&As[1][0][0]) };
    const uint32_t bs_base[2] = { smem_u32(&Bs[0][0][0]), smem_u32(&Bs[1][0][0]) };

    float s8[8], zs8[8];

    auto load_group = [&](int g) {
        unsigned zw = (unsigned)qz[(size_t)g * NP + (bn >> 3) + pc];
        float4 slo = *reinterpret_cast<const float4*>(&sc[(size_t)g * NN + bn + pc * 8]);
        float4 shi = *reinterpret_cast<const float4*>(&sc[(size_t)g * NN + bn + pc * 8 + 4]);
        s8[0] = slo.x; s8[1] = slo.y; s8[2] = slo.z; s8[3] = slo.w;
        s8[4] = shi.x; s8[5] = shi.y; s8[6] = shi.z; s8[7] = shi.w;
#pragma unroll
        for (int j = 0; j < 8; ++j)
            zs8[j] = -(float)((zw >> awq_shift(j)) & 0xF) * s8[j];
    };

    auto load_a = [&](int it, int s) {
        const int k0 = it * BK;
#pragma unroll
        for (int i = 0; i < 2; ++i) {
            const int row = ar + i * 64;
            const uint32_t dst = as_base[s] + (uint32_t)(row * AK + ac) * 2;
            cp_async16(dst, &g_xh[(size_t)(bm + row) * KK + k0 + ac]);
        }
        cp_commit();
    };

    auto dequant_b = [&](int it, int s) {
        const int k0 = it * BK;
#pragma unroll
        for (int i = 0; i < 2; ++i) {
            const int k = kq + i * 16;
            unsigned wv = (unsigned)qw[(size_t)(k0 + k) * NP + (bn >> 3) + pc];
            uint32_t h[4];
#pragma unroll
            for (int p = 0; p < 4; ++p) {
                float f0 = fmaf((float)((wv >> (4 * p)) & 0xF),       s8[2 * p],     zs8[2 * p]);
                float f1 = fmaf((float)((wv >> (4 * p + 16)) & 0xF),  s8[2 * p + 1], zs8[2 * p + 1]);
                __half2 hh = __floats2half2_rn(f0, f1);
                h[p] = *reinterpret_cast<uint32_t*>(&hh);
            }
            const uint32_t dst = bs_base[s] + (uint32_t)(k * BNP + pc * 8) * 2;
            asm volatile("st.shared.v4.b32 [%0], {%1,%2,%3,%4};"
                         :: "r"(dst), "r"(h[0]), "r"(h[1]), "r"(h[2]), "r"(h[3]) : "memory");
        }
    };

    float acc[2][8][4];
#pragma unroll
    for (int mt = 0; mt < 2; ++mt)
#pragma unroll
        for (int nt = 0; nt < 8; ++nt)
#pragma unroll
            for (int q = 0; q < 4; ++q) acc[mt][nt][q] = 0.f;

    // prologue
    load_group(0);
    load_a(0, 0);
    dequant_b(0, 0);

    const int lr = lane & 15;            // ldmatrix row select
    const int lc = (lane >> 4) * 8;      // ldmatrix col select (halves)

    for (int it = 0; it < KTILES; ++it) {
        const int s = it & 1;
        if (it + 1 < KTILES) {
            if (((it + 1) & 3) == 0) load_group((it + 1) >> 2);
            load_a(it + 1, s ^ 1);
            dequant_b(it + 1, s ^ 1);
            cp_wait<1>();
        } else {
            cp_wait<0>();
        }
        __syncthreads();

        // compute stage s
#pragma unroll
        for (int ks = 0; ks < 2; ++ks) {
            const int k16 = ks * 16;
            uint32_t afr[2][4];
#pragma unroll
            for (int mt = 0; mt < 2; ++mt) {
                const int row = wm * 32 + mt * 16 + lr;
                ldsm_x4(afr[mt], as_base[s] + (uint32_t)(row * AK + k16 + lc) * 2);
            }
            uint32_t bfr[4][4];
#pragma unroll
            for (int bq = 0; bq < 4; ++bq) {
                const int col = wn * 64 + bq * 16 + lc;
                ldsm_x4_t(bfr[bq], bs_base[s] + (uint32_t)((k16 + lr) * BNP + col) * 2);
            }
#pragma unroll
            for (int mt = 0; mt < 2; ++mt)
#pragma unroll
                for (int bq = 0; bq < 4; ++bq) {
                    mma16816(acc[mt][2 * bq + 0], afr[mt], &bfr[bq][0]);
                    mma16816(acc[mt][2 * bq + 1], afr[mt], &bfr[bq][2]);
                }
        }
        __syncthreads();
    }

    // epilogue: direct fp32 stores (float2 per c-frag half)
    const int gid = lane >> 2;
    const int tig = lane & 3;
#pragma unroll
    for (int mt = 0; mt < 2; ++mt) {
#pragma unroll
        for (int nt = 0; nt < 8; ++nt) {
            const int n = bn + wn * 64 + nt * 8 + tig * 2;
            const int m0 = bm + wm * 32 + mt * 16 + gid;
            float2 v0 = make_float2(acc[mt][nt][0], acc[mt][nt][1]);
            float2 v1 = make_float2(acc[mt][nt][2], acc[mt][nt][3]);
            *reinterpret_cast<float2*>(&out[(size_t)m0 * NN + n]) = v0;
            *reinterpret_cast<float2*>(&out[(size_t)(m0 + 8) * NN + n]) = v1;
        }
    }
}

extern "C" void kernel_launch(void* const* d_in, const int* in_sizes, int n_in,
                              void* d_out, int out_size)
{
    const float* x  = (const float*)d_in[0];
    const int*   qw = (const int*)  d_in[1];
    const int*   qz = (const int*)  d_in[2];
    const float* sc = (const float*)d_in[3];
    float*       out = (float*)d_out;

    conv_x_kernel<<<(int)((size_t)MM * KK / 8 / 256), 256>>>(x);

    dim3 grid(NN / BN, MM / BM);   // 86 x 16
    awq_mma_kernel<<<grid, THREADS>>>(qw, qz, sc, out);
}